// round 1
// baseline (speedup 1.0000x reference)
#include <cuda_runtime.h>
#include <cstdint>

// Problem constants (fixed by the reference)
#define N_TOK   4096
#define DIM     4096
#define OUT_DIM 4096
#define NE      8
#define NH      3
#define NR      16
#define NJ      160            // 8 router + 128 a (E*R) + 24 head (E*H)
#define NU      384            // E*H*R
#define SCALE_F 2.0f           // lora_alpha / r = 32/16

// Scratch: per-token fused LoRA coefficient vector u[n, (e*H+h)*R+r]
__device__ float g_u[N_TOK * NU];

// ============================================================================
// Kernel 1: per-token router logits, head logits, a = x@A; then softmax/top-2
// gating and construction of u. Tiled as a [32 tokens] x [160 outputs] GEMM
// over K=4096 so all weights stay in L2 across blocks.
// ============================================================================
__global__ __launch_bounds__(256) void moe_prep_kernel(
    const float* __restrict__ x,       // [N, D]
    const float* __restrict__ routerW, // [E, D]
    const float* __restrict__ A,       // [E, D, R]
    const float* __restrict__ Rm)      // [E, D, H]
{
    __shared__ float xs[32][32];       // 4 KB
    __shared__ float ws[32][NJ];       // 20 KB
    __shared__ float tbuf[32][NJ];     // 20 KB
    __shared__ float coeff[32][24];    // 3 KB  (E*H per token)

    const int tid   = threadIdx.x;
    const int jlane = tid & 31;        // output lane (32)
    const int ty    = tid >> 5;        // token lane (8)
    const int tok0  = blockIdx.x * 32;

    float acc[4][5];
    #pragma unroll
    for (int a0 = 0; a0 < 4; a0++)
        #pragma unroll
        for (int b0 = 0; b0 < 5; b0++) acc[a0][b0] = 0.f;

    for (int k0 = 0; k0 < DIM; k0 += 32) {
        // load x tile [32 tokens][32 k]: 256 float4, one per thread
        {
            int row = tid >> 3, kq = tid & 7;
            float4 v = *reinterpret_cast<const float4*>(
                x + (size_t)(tok0 + row) * DIM + k0 + kq * 4);
            xs[row][kq * 4 + 0] = v.x;
            xs[row][kq * 4 + 1] = v.y;
            xs[row][kq * 4 + 2] = v.z;
            xs[row][kq * 4 + 3] = v.w;
        }
        // gather weight tile [32 k][160 j] from the three weight tensors
        for (int idx = tid; idx < 32 * NJ; idx += 256) {
            int d = idx / NJ, j = idx - d * NJ;
            int dd = k0 + d;
            float w;
            if (j < 8) {
                w = routerW[j * DIM + dd];
            } else if (j < 136) {
                int e = (j - 8) >> 4, r = (j - 8) & 15;
                w = A[((size_t)e * DIM + dd) * NR + r];
            } else {
                int e = (j - 136) / 3, h = (j - 136) - e * 3;
                w = Rm[((size_t)e * DIM + dd) * NH + h];
            }
            ws[d][j] = w;
        }
        __syncthreads();

        #pragma unroll
        for (int kk = 0; kk < 32; kk++) {
            float xv[4];
            #pragma unroll
            for (int tt = 0; tt < 4; tt++) xv[tt] = xs[ty + 8 * tt][kk];
            #pragma unroll
            for (int jj = 0; jj < 5; jj++) {
                float wv = ws[kk][jlane + 32 * jj];
                #pragma unroll
                for (int tt = 0; tt < 4; tt++) acc[tt][jj] += xv[tt] * wv;
            }
        }
        __syncthreads();
    }

    // stash full per-token result rows
    #pragma unroll
    for (int tt = 0; tt < 4; tt++)
        #pragma unroll
        for (int jj = 0; jj < 5; jj++)
            tbuf[ty + 8 * tt][jlane + 32 * jj] = acc[tt][jj];

    for (int idx = tid; idx < 32 * 24; idx += 256)
        coeff[idx / 24][idx % 24] = 0.f;
    __syncthreads();

    // one thread per token: top-2 gate + per-expert head softmax -> coeff
    if (tid < 32) {
        int t = tid;
        int i1 = 0;
        #pragma unroll
        for (int e = 1; e < NE; e++) if (tbuf[t][e] > tbuf[t][i1]) i1 = e;
        int i2 = (i1 == 0) ? 1 : 0;
        #pragma unroll
        for (int e = 0; e < NE; e++)
            if (e != i1 && tbuf[t][e] > tbuf[t][i2]) i2 = e;

        float ed = expf(tbuf[t][i2] - tbuf[t][i1]);   // <= 1
        float g1 = 1.f / (1.f + ed);
        float g2 = ed / (1.f + ed);

        int   ids[2] = {i1, i2};
        float gs[2]  = {g1, g2};
        #pragma unroll
        for (int p = 0; p < 2; p++) {
            int e = ids[p];
            float h0 = tbuf[t][136 + e * 3 + 0];
            float h1 = tbuf[t][136 + e * 3 + 1];
            float h2 = tbuf[t][136 + e * 3 + 2];
            float m  = fmaxf(h0, fmaxf(h1, h2));
            float x0 = expf(h0 - m), x1 = expf(h1 - m), x2 = expf(h2 - m);
            float inv = gs[p] * SCALE_F / (x0 + x1 + x2);
            coeff[t][e * 3 + 0] = x0 * inv;
            coeff[t][e * 3 + 1] = x1 * inv;
            coeff[t][e * 3 + 2] = x2 * inv;
        }
    }
    __syncthreads();

    // u[t, e*48 + h*16 + r] = coeff[t][e*3+h] * a[t][e*16+r]
    for (int idx = tid; idx < 32 * NU; idx += 256) {
        int t = idx / NU, j = idx - t * NU;
        int e = j / 48;
        int jr = j - e * 48;
        int h = jr >> 4, r = jr & 15;
        g_u[(size_t)(tok0 + t) * NU + j] = coeff[t][e * 3 + h] * tbuf[t][8 + e * 16 + r];
    }
}

// ============================================================================
// Kernel 2: out = x @ base_W + u @ Bflat   (single fused K loop: 4096 + 384)
// TF32 mma.sync m16n8k8, 128x128x16 block tile, 2x4 warp grid, 64x32 warp tile,
// double-buffered SMEM, cvt.rna.tf32 applied at SMEM-store time.
// ============================================================================
#define BM 128
#define BN 128
#define BK 16
#define AS_STR 20    // pad for conflict-free frag reads
#define BS_STR 132
#define KT1 (DIM / BK)   // 256
#define KT2 (NU  / BK)   // 24
#define KT_ALL (KT1 + KT2)

__device__ __forceinline__ uint32_t f2tf32(float f) {
    uint32_t u;
    asm("cvt.rna.tf32.f32 %0, %1;" : "=r"(u) : "f"(f));
    return u;
}

__global__ __launch_bounds__(256) void fused_gemm_kernel(
    const float* __restrict__ x,      // [N, D]
    const float* __restrict__ baseW,  // [D, O]
    const float* __restrict__ Bfl,    // [NU, O] (== B tensor flattened)
    float* __restrict__ out)          // [N, O]
{
    __shared__ __align__(16) float As[2][BM][AS_STR];
    __shared__ __align__(16) float Bs[2][BK][BS_STR];

    const int tid  = threadIdx.x;
    const int lane = tid & 31, warp = tid >> 5;
    const int wm = warp & 1, wn = warp >> 1;     // 2 x 4 warp grid
    const int g  = lane >> 2, tg = lane & 3;
    const int m0 = blockIdx.y * BM;
    const int n0 = blockIdx.x * BN;

    // global-load coordinates
    const int arow = tid >> 2;         // 0..63 (second load +64)
    const int akq  = tid & 3;          // float4 slot within 16-wide row
    const int brow = tid >> 5;         // 0..7  (second load +8)
    const int bq   = tid & 31;         // float4 slot within 128-wide row

    float c[4][4][4];
    #pragma unroll
    for (int i = 0; i < 4; i++)
        #pragma unroll
        for (int j = 0; j < 4; j++)
            #pragma unroll
            for (int k = 0; k < 4; k++) c[i][j][k] = 0.f;

    float4 la0, la1, lb0, lb1;

    auto load_tile = [&](int kt) {
        const float* Ab; const float* Bb; int lda;
        if (kt < KT1) {
            Ab  = x + (size_t)kt * BK;
            lda = DIM;
            Bb  = baseW + (size_t)kt * BK * OUT_DIM;
        } else {
            int k2 = kt - KT1;
            Ab  = g_u + (size_t)k2 * BK;
            lda = NU;
            Bb  = Bfl + (size_t)k2 * BK * OUT_DIM;
        }
        la0 = *reinterpret_cast<const float4*>(Ab + (size_t)(m0 + arow)      * lda + akq * 4);
        la1 = *reinterpret_cast<const float4*>(Ab + (size_t)(m0 + arow + 64) * lda + akq * 4);
        lb0 = *reinterpret_cast<const float4*>(Bb + (size_t)brow       * OUT_DIM + n0 + bq * 4);
        lb1 = *reinterpret_cast<const float4*>(Bb + (size_t)(brow + 8) * OUT_DIM + n0 + bq * 4);
    };

    auto stage_tile = [&](int buf) {
        uint4 a0 = {f2tf32(la0.x), f2tf32(la0.y), f2tf32(la0.z), f2tf32(la0.w)};
        uint4 a1 = {f2tf32(la1.x), f2tf32(la1.y), f2tf32(la1.z), f2tf32(la1.w)};
        uint4 b0 = {f2tf32(lb0.x), f2tf32(lb0.y), f2tf32(lb0.z), f2tf32(lb0.w)};
        uint4 b1 = {f2tf32(lb1.x), f2tf32(lb1.y), f2tf32(lb1.z), f2tf32(lb1.w)};
        *reinterpret_cast<uint4*>(&As[buf][arow][akq * 4])      = a0;
        *reinterpret_cast<uint4*>(&As[buf][arow + 64][akq * 4]) = a1;
        *reinterpret_cast<uint4*>(&Bs[buf][brow][bq * 4])       = b0;
        *reinterpret_cast<uint4*>(&Bs[buf][brow + 8][bq * 4])   = b1;
    };

    load_tile(0);
    stage_tile(0);
    __syncthreads();

    int buf = 0;
    for (int kt = 0; kt < KT_ALL; kt++) {
        if (kt + 1 < KT_ALL) load_tile(kt + 1);

        #pragma unroll
        for (int ks = 0; ks < 2; ks++) {
            const int k8 = ks * 8;
            uint32_t af[4][4], bf[4][2];
            #pragma unroll
            for (int im = 0; im < 4; im++) {
                int r = wm * 64 + im * 16;
                af[im][0] = __float_as_uint(As[buf][r + g][k8 + tg]);
                af[im][1] = __float_as_uint(As[buf][r + g + 8][k8 + tg]);
                af[im][2] = __float_as_uint(As[buf][r + g][k8 + tg + 4]);
                af[im][3] = __float_as_uint(As[buf][r + g + 8][k8 + tg + 4]);
            }
            #pragma unroll
            for (int in = 0; in < 4; in++) {
                int cc = wn * 32 + in * 8 + g;
                bf[in][0] = __float_as_uint(Bs[buf][k8 + tg][cc]);
                bf[in][1] = __float_as_uint(Bs[buf][k8 + tg + 4][cc]);
            }
            #pragma unroll
            for (int im = 0; im < 4; im++)
                #pragma unroll
                for (int in = 0; in < 4; in++) {
                    asm volatile(
                        "mma.sync.aligned.m16n8k8.row.col.f32.tf32.tf32.f32 "
                        "{%0,%1,%2,%3}, {%4,%5,%6,%7}, {%8,%9}, {%0,%1,%2,%3};\n"
                        : "+f"(c[im][in][0]), "+f"(c[im][in][1]),
                          "+f"(c[im][in][2]), "+f"(c[im][in][3])
                        : "r"(af[im][0]), "r"(af[im][1]), "r"(af[im][2]), "r"(af[im][3]),
                          "r"(bf[in][0]), "r"(bf[in][1]));
                }
        }

        if (kt + 1 < KT_ALL) {
            stage_tile(buf ^ 1);
            __syncthreads();
            buf ^= 1;
        }
    }

    // epilogue: fp32 stores, float2-vectorized
    #pragma unroll
    for (int im = 0; im < 4; im++) {
        int row = m0 + wm * 64 + im * 16 + g;
        #pragma unroll
        for (int in = 0; in < 4; in++) {
            int col = n0 + wn * 32 + in * 8 + 2 * tg;
            float2 v0 = make_float2(c[im][in][0], c[im][in][1]);
            float2 v1 = make_float2(c[im][in][2], c[im][in][3]);
            *reinterpret_cast<float2*>(&out[(size_t)row * OUT_DIM + col])       = v0;
            *reinterpret_cast<float2*>(&out[(size_t)(row + 8) * OUT_DIM + col]) = v1;
        }
    }
}

// ============================================================================
extern "C" void kernel_launch(void* const* d_in, const int* in_sizes, int n_in,
                              void* d_out, int out_size) {
    const float* x       = (const float*)d_in[0];  // [4096, 4096]
    const float* baseW   = (const float*)d_in[1];  // [4096, 4096]
    const float* routerW = (const float*)d_in[2];  // [8, 4096]
    const float* A       = (const float*)d_in[3];  // [8, 4096, 16]
    const float* B       = (const float*)d_in[4];  // [8, 3, 16, 4096] -> Bflat [384, 4096]
    const float* Rm      = (const float*)d_in[5];  // [8, 4096, 3]
    float* out = (float*)d_out;

    moe_prep_kernel<<<N_TOK / 32, 256>>>(x, routerW, A, Rm);
    fused_gemm_kernel<<<dim3(OUT_DIM / BN, N_TOK / BM), 256>>>(x, baseW, B, out);
}

// round 3
// speedup vs baseline: 2.4470x; 2.4470x over previous
#include <cuda_runtime.h>
#include <cstdint>

// ---------------------------------------------------------------------------
// Problem constants
// ---------------------------------------------------------------------------
#define N_TOK   4096
#define DIM     4096
#define OUT_DIM 4096
#define NE      8
#define NH      3
#define NR      16
#define NU      384
#define K_ALL   (DIM + NU)     // 4480
#define SCALE_F 2.0f
#define NWG     256            // padded prep-weight rows (128 a + 24 head + pad)

// Scratch (static device arrays; no runtime allocation)
__device__ float g_Xr[(size_t)N_TOK * K_ALL];    // [N][4480] rna(x) | rna(u)
__device__ float g_Wt[(size_t)OUT_DIM * K_ALL];  // [O][4480] rna([baseW;Bfl]^T)
__device__ float g_Wg[(size_t)NWG * DIM];        // [256][4096] gathered A,R (k-major)
__device__ float g_P [(size_t)N_TOK * NWG];      // [N][256] prep GEMM out

__device__ __forceinline__ uint32_t f2tf32(float f) {
    uint32_t u;
    asm("cvt.rna.tf32.f32 %0, %1;" : "=r"(u) : "f"(f));
    return u;
}

// ---------------------------------------------------------------------------
// K1: Xr[:, 0:4096] = rna(x)
// ---------------------------------------------------------------------------
__global__ __launch_bounds__(256) void round_x_kernel(const float* __restrict__ x) {
    size_t id  = (size_t)blockIdx.x * blockDim.x + threadIdx.x;  // one float4 each
    size_t row = id >> 10;
    size_t q   = id & 1023;
    float4 v = *reinterpret_cast<const float4*>(x + row * DIM + q * 4);
    float4 o;
    o.x = __uint_as_float(f2tf32(v.x));
    o.y = __uint_as_float(f2tf32(v.y));
    o.z = __uint_as_float(f2tf32(v.z));
    o.w = __uint_as_float(f2tf32(v.w));
    *reinterpret_cast<float4*>(g_Xr + row * K_ALL + q * 4) = o;
}

// ---------------------------------------------------------------------------
// K2: Wt[n][k] = rna( k<4096 ? baseW[k][n] : Bfl[k-4096][n] )
// ---------------------------------------------------------------------------
__global__ __launch_bounds__(256) void transpose_w_kernel(
    const float* __restrict__ baseW, const float* __restrict__ Bfl) {
    __shared__ float tile[32][33];
    const int tx = threadIdx.x & 31, ty = threadIdx.x >> 5;
    const int kb = blockIdx.x * 32, nb = blockIdx.y * 32;
    #pragma unroll
    for (int i = 0; i < 4; i++) {
        int k = kb + ty + 8 * i;
        int n = nb + tx;
        float v = (k < DIM) ? baseW[(size_t)k * OUT_DIM + n]
                            : Bfl[(size_t)(k - DIM) * OUT_DIM + n];
        tile[ty + 8 * i][tx] = __uint_as_float(f2tf32(v));
    }
    __syncthreads();
    #pragma unroll
    for (int i = 0; i < 4; i++) {
        int n = nb + ty + 8 * i;
        int k = kb + tx;
        g_Wt[(size_t)n * K_ALL + k] = tile[tx][ty + 8 * i];
    }
}

// ---------------------------------------------------------------------------
// K3: gather Wg[256][4096]: rows 0..127 = A[e][:,r], 128..151 = Rm[e][:,h], rest 0
// ---------------------------------------------------------------------------
__global__ __launch_bounds__(256) void gather_wg_kernel(
    const float* __restrict__ A, const float* __restrict__ Rm) {
    int idx = blockIdx.x * 256 + threadIdx.x;     // 256*4096 total
    int j = idx >> 12, d = idx & 4095;
    float v = 0.f;
    if (j < 128) {
        int e = j >> 4, r = j & 15;
        v = A[((size_t)e * DIM + d) * NR + r];
    } else if (j < 152) {
        int jj = j - 128, e = jj / 3, h = jj - 3 * e;
        v = Rm[((size_t)e * DIM + d) * NH + h];
    }
    g_Wg[(size_t)j * DIM + d] = __uint_as_float(f2tf32(v));
}

// ---------------------------------------------------------------------------
// K4: tensor-core GEMM  out[M][ldo] = Ag[M][lda] @ Bg[N][ldb]^T   (both K-major)
// 128x128x32 tiles, 3-stage cp.async pipeline, XOR-swizzled smem, mma.sync TF32.
// Inputs must already be tf32-rounded.
// ---------------------------------------------------------------------------
#define BM 128
#define BN 128
#define BKF 32
#define NSTAGE 3
#define TILEB 16384                  // 128 rows * 32 floats * 4B

__device__ __forceinline__ void cp16(uint32_t daddr, const float* gptr) {
    asm volatile("cp.async.cg.shared.global [%0], [%1], 16;"
                 :: "r"(daddr), "l"(gptr) : "memory");
}
__device__ __forceinline__ uint32_t lds32(uint32_t a) {
    uint32_t v;
    asm volatile("ld.shared.b32 %0, [%1];" : "=r"(v) : "r"(a));
    return v;
}
__device__ __forceinline__ uint32_t smem_u32(const void* p) {
    uint32_t a;
    asm("{ .reg .u64 t; cvta.to.shared.u64 t, %1; cvt.u32.u64 %0, t; }" : "=r"(a) : "l"(p));
    return a;
}

__global__ __launch_bounds__(256, 2) void mma_gemm_kernel(
    const float* __restrict__ Ag, int lda,
    const float* __restrict__ Bg, int ldb,
    float* __restrict__ out, int ldo, int ksteps)
{
    extern __shared__ __align__(1024) float sm[];
    const uint32_t smu = smem_u32(sm);
    const uint32_t smuB = smu + NSTAGE * TILEB;

    const int tid = threadIdx.x, lane = tid & 31, warp = tid >> 5;
    const int wm = warp & 1, wn = warp >> 1;
    const int g = lane >> 2, tg = lane & 3;
    const int m0 = blockIdx.y * BM, n0 = blockIdx.x * BN;

    const int lrow = tid >> 3;      // 0..31
    const int lkq  = tid & 7;       // 16B granule in 128B row

    float c[4][4][4];
    #pragma unroll
    for (int i = 0; i < 4; i++)
        #pragma unroll
        for (int j = 0; j < 4; j++)
            #pragma unroll
            for (int k = 0; k < 4; k++) c[i][j][k] = 0.f;

    auto issue = [&](int kt, int s) {
        const float* abase = Ag + (size_t)(m0 + lrow) * lda + kt * BKF + lkq * 4;
        const float* bbase = Bg + (size_t)(n0 + lrow) * ldb + kt * BKF + lkq * 4;
        #pragma unroll
        for (int i = 0; i < 4; i++) {
            int m = lrow + 32 * i;
            uint32_t gran = (uint32_t)(m * 8 + (lkq ^ (m & 7))) * 16;
            cp16(smu  + s * TILEB + gran, abase + (size_t)(32 * i) * lda);
            cp16(smuB + s * TILEB + gran, bbase + (size_t)(32 * i) * ldb);
        }
    };

    // prologue: stages 0..NSTAGE-2
    #pragma unroll
    for (int s = 0; s < NSTAGE - 1; s++) {
        issue(s, s);
        asm volatile("cp.async.commit_group;" ::: "memory");
    }

    for (int kt = 0; kt < ksteps; kt++) {
        const int cur = kt % NSTAGE;
        asm volatile("cp.async.wait_group %0;" :: "n"(NSTAGE - 2) : "memory");
        __syncthreads();

        int nk = kt + NSTAGE - 1;
        if (nk < ksteps) issue(nk, nk % NSTAGE);
        asm volatile("cp.async.commit_group;" ::: "memory");

        const uint32_t sA = smu  + cur * TILEB + wm * 64 * 128;
        const uint32_t sB = smuB + cur * TILEB + wn * 32 * 128;

        #pragma unroll
        for (int k8 = 0; k8 < BKF; k8 += 8) {
            const uint32_t kx0 = (uint32_t)((k8 + tg)     ^ (g << 2)) * 4;
            const uint32_t kx1 = (uint32_t)((k8 + tg + 4) ^ (g << 2)) * 4;
            uint32_t af[4][4], bf[4][2];
            #pragma unroll
            for (int im = 0; im < 4; im++) {
                uint32_t ra = sA + (im * 16 + g) * 128;
                af[im][0] = lds32(ra + kx0);
                af[im][1] = lds32(ra + 8 * 128 + kx0);
                af[im][2] = lds32(ra + kx1);
                af[im][3] = lds32(ra + 8 * 128 + kx1);
            }
            #pragma unroll
            for (int in = 0; in < 4; in++) {
                uint32_t rb = sB + (in * 8 + g) * 128;
                bf[in][0] = lds32(rb + kx0);
                bf[in][1] = lds32(rb + kx1);
            }
            #pragma unroll
            for (int im = 0; im < 4; im++)
                #pragma unroll
                for (int in = 0; in < 4; in++) {
                    asm volatile(
                        "mma.sync.aligned.m16n8k8.row.col.f32.tf32.tf32.f32 "
                        "{%0,%1,%2,%3}, {%4,%5,%6,%7}, {%8,%9}, {%0,%1,%2,%3};\n"
                        : "+f"(c[im][in][0]), "+f"(c[im][in][1]),
                          "+f"(c[im][in][2]), "+f"(c[im][in][3])
                        : "r"(af[im][0]), "r"(af[im][1]), "r"(af[im][2]), "r"(af[im][3]),
                          "r"(bf[in][0]), "r"(bf[in][1]));
                }
        }
    }

    // epilogue (layout validated in R1)
    #pragma unroll
    for (int im = 0; im < 4; im++) {
        int row = m0 + wm * 64 + im * 16 + g;
        #pragma unroll
        for (int in = 0; in < 4; in++) {
            int col = n0 + wn * 32 + in * 8 + 2 * tg;
            float2 v0 = make_float2(c[im][in][0], c[im][in][1]);
            float2 v1 = make_float2(c[im][in][2], c[im][in][3]);
            *reinterpret_cast<float2*>(&out[(size_t)row * ldo + col])       = v0;
            *reinterpret_cast<float2*>(&out[(size_t)(row + 8) * ldo + col]) = v1;
        }
    }
}

// ---------------------------------------------------------------------------
// K5: finalize — exact router logits (fp32), top-2 gates, head softmax from P,
// u = coeff * a written (rna) into Xr[:, 4096:4480]. 16 tokens / block.
// ---------------------------------------------------------------------------
__global__ __launch_bounds__(512) void finalize_kernel(
    const float* __restrict__ x, const float* __restrict__ routerW)
{
    extern __shared__ float rw[];               // [NE * DIM] = 128KB
    __shared__ float scoeff[16][24];

    const int tid = threadIdx.x, lane = tid & 31, warp = tid >> 5;
    const int token = blockIdx.x * 16 + warp;

    for (int i = tid; i < NE * DIM / 4; i += 512)
        reinterpret_cast<float4*>(rw)[i] = reinterpret_cast<const float4*>(routerW)[i];
    __syncthreads();

    // exact router logits
    float acc[NE];
    #pragma unroll
    for (int e = 0; e < NE; e++) acc[e] = 0.f;
    const float* xrow = x + (size_t)token * DIM;
    for (int i = lane; i < DIM; i += 32) {
        float xv = __ldg(xrow + i);
        #pragma unroll
        for (int e = 0; e < NE; e++) acc[e] += xv * rw[e * DIM + i];
    }
    #pragma unroll
    for (int e = 0; e < NE; e++)
        #pragma unroll
        for (int o = 16; o > 0; o >>= 1)
            acc[e] += __shfl_xor_sync(0xffffffffu, acc[e], o);

    if (lane == 0) {
        int i1 = 0;
        #pragma unroll
        for (int e = 1; e < NE; e++) if (acc[e] > acc[i1]) i1 = e;
        int i2 = (i1 == 0) ? 1 : 0;
        #pragma unroll
        for (int e = 0; e < NE; e++)
            if (e != i1 && acc[e] > acc[i2]) i2 = e;

        float ed = expf(acc[i2] - acc[i1]);
        float g1 = 1.f / (1.f + ed);
        float g2 = ed / (1.f + ed);

        #pragma unroll
        for (int q = 0; q < 24; q++) scoeff[warp][q] = 0.f;

        int   ids[2] = {i1, i2};
        float gs[2]  = {g1, g2};
        const float* Prow = g_P + (size_t)token * NWG;
        #pragma unroll
        for (int p = 0; p < 2; p++) {
            int e = ids[p];
            float h0 = Prow[128 + e * 3 + 0];
            float h1 = Prow[128 + e * 3 + 1];
            float h2 = Prow[128 + e * 3 + 2];
            float m  = fmaxf(h0, fmaxf(h1, h2));
            float x0 = expf(h0 - m), x1 = expf(h1 - m), x2 = expf(h2 - m);
            float inv = gs[p] * SCALE_F / (x0 + x1 + x2);
            scoeff[warp][e * 3 + 0] = x0 * inv;
            scoeff[warp][e * 3 + 1] = x1 * inv;
            scoeff[warp][e * 3 + 2] = x2 * inv;
        }
    }
    __syncwarp();

    const float* Prow = g_P + (size_t)token * NWG;
    #pragma unroll
    for (int rep = 0; rep < NU / 32; rep++) {
        int j = lane + 32 * rep;             // 0..383
        int e = j / 48;
        int jr = j - e * 48;
        int h = jr >> 4, r = jr & 15;
        float u = scoeff[warp][e * 3 + h] * Prow[e * 16 + r];
        g_Xr[(size_t)token * K_ALL + DIM + j] = __uint_as_float(f2tf32(u));
    }
}

// ---------------------------------------------------------------------------
// host launch
// ---------------------------------------------------------------------------
extern "C" void kernel_launch(void* const* d_in, const int* in_sizes, int n_in,
                              void* d_out, int out_size) {
    const float* x       = (const float*)d_in[0];
    const float* baseW   = (const float*)d_in[1];
    const float* routerW = (const float*)d_in[2];
    const float* A       = (const float*)d_in[3];
    const float* B       = (const float*)d_in[4];
    const float* Rm      = (const float*)d_in[5];
    float* out = (float*)d_out;

    void *pXr = nullptr, *pWt = nullptr, *pWg = nullptr, *pP = nullptr;
    cudaGetSymbolAddress(&pXr, g_Xr);
    cudaGetSymbolAddress(&pWt, g_Wt);
    cudaGetSymbolAddress(&pWg, g_Wg);
    cudaGetSymbolAddress(&pP,  g_P);

    static bool attr_set = false;
    if (!attr_set) {
        cudaFuncSetAttribute(mma_gemm_kernel,
                             cudaFuncAttributeMaxDynamicSharedMemorySize,
                             2 * NSTAGE * TILEB);
        cudaFuncSetAttribute(finalize_kernel,
                             cudaFuncAttributeMaxDynamicSharedMemorySize,
                             NE * DIM * sizeof(float));
        attr_set = true;
    }

    // 1) round x into Xr
    round_x_kernel<<<(N_TOK * (DIM / 4)) / 256, 256>>>(x);
    // 2) W^T (rounded) for the main GEMM
    transpose_w_kernel<<<dim3(K_ALL / 32, OUT_DIM / 32), 256>>>(baseW, B);
    // 3) gathered prep weights
    gather_wg_kernel<<<(NWG * DIM) / 256, 256>>>(A, Rm);
    // 4) prep GEMM: P = Xr[:, :4096] @ Wg^T
    mma_gemm_kernel<<<dim3(NWG / BN, N_TOK / BM), 256, 2 * NSTAGE * TILEB>>>(
        (const float*)pXr, K_ALL, (const float*)pWg, DIM,
        (float*)pP, NWG, DIM / BKF);
    // 5) gates + head softmax + u -> Xr[:, 4096:]
    finalize_kernel<<<N_TOK / 16, 512, NE * DIM * sizeof(float)>>>(x, routerW);
    // 6) main GEMM: out = Xr @ Wt^T
    mma_gemm_kernel<<<dim3(OUT_DIM / BN, N_TOK / BM), 256, 2 * NSTAGE * TILEB>>>(
        (const float*)pXr, K_ALL, (const float*)pWt, K_ALL,
        out, OUT_DIM, K_ALL / BKF);
}